// round 3
// baseline (speedup 1.0000x reference)
#include <cuda_runtime.h>
#include <cuda_bf16.h>

// Problem constants
#define BB 8
#define NN 65536
#define PP 12
#define GG 64
#define G3 (GG*GG*GG)               // 262144
#define THREADS 256
#define NBLOCKS ((BB*NN)/THREADS)   // 2048

// Scratch (static device arrays — no dynamic allocation anywhere)
__device__ float4 g_norm_planes[BB*PP];
__device__ float  g_partials[NBLOCKS];

// ---------------------------------------------------------------------------
// Kernel 1: normalize the 96 planes once.
// ref: ns_norm = ||n||; ds = d/||n||; ns = n/||n||
// ---------------------------------------------------------------------------
__global__ void normalize_planes_kernel(const float* __restrict__ planes) {
    int i = threadIdx.x;
    if (i < BB*PP) {
        float nx = planes[i*4+0];
        float ny = planes[i*4+1];
        float nz = planes[i*4+2];
        float d  = planes[i*4+3];
        float norm = sqrtf(nx*nx + ny*ny + nz*nz);
        g_norm_planes[i] = make_float4(nx/norm, ny/norm, nz/norm, d/norm);
    }
}

// ---------------------------------------------------------------------------
// Kernel 2: main. One thread per (b, point); each thread owns the 12 flat
// positions f = pt*12+k of the reference's (b, p*n) flattening, so
// plane = f >> 16 (N = 2^16). This reproduces the reference's
// reshape-reinterpretation of the broadcast (b,n,p,3) array into (b,p,n,3).
//
// refl = p - 2*(dot(p,n)+d)*n
// idx3 = ceil((refl+0.5)*G - 0.5)   (rn adds/muls, no fma fusion)
// idx  = clip(ix*G*G + iy*G + iz, 0, G^3-1)
// term = ||refl - cp[idx]||^2 * (1 - voxel[idx]),   voxel in {0,1}
//
// Phase A: compute all 12 reflections+indices, then issue all 12 voxel
//          gathers back-to-back (independent -> MLP=12, hides L2 latency).
// Phase B: masked cp gathers + accumulate.
// ---------------------------------------------------------------------------
__global__ __launch_bounds__(THREADS)
void sym_plane_loss_kernel(const float* __restrict__ voxel,
                           const float* __restrict__ points,
                           const float* __restrict__ cp)
{
    const int t  = blockIdx.x * THREADS + threadIdx.x;   // 0 .. B*N-1
    const int b  = t >> 16;            // N = 65536
    const int pt = t & 0xFFFF;

    const float px = __ldg(points + t*3 + 0);
    const float py = __ldg(points + t*3 + 1);
    const float pz = __ldg(points + t*3 + 2);

    const float* __restrict__ vox_b = voxel + b * G3;
    const float* __restrict__ cp_b  = cp    + (size_t)b * G3 * 3;
    const float4* __restrict__ pl_b = g_norm_planes + b * PP;

    const int base_f = pt * PP;

    float rxs[PP], rys[PP], rzs[PP];
    int   idxs[PP];
    float vs[PP];

    // ---- Phase A: reflections + indices ----
    #pragma unroll
    for (int k = 0; k < PP; k++) {
        const int f     = base_f + k;
        const int plane = f >> 16;          // f / N
        const float4 n4 = pl_b[plane];

        const float dot = px*n4.x + py*n4.y + pz*n4.z;
        const float s   = 2.0f * (dot + n4.w);
        const float rx  = px - s * n4.x;
        const float ry  = py - s * n4.y;
        const float rz  = pz - s * n4.z;

        const int ix = (int)ceilf(__fadd_rn(__fmul_rn(__fadd_rn(rx, 0.5f), (float)GG), -0.5f));
        const int iy = (int)ceilf(__fadd_rn(__fmul_rn(__fadd_rn(ry, 0.5f), (float)GG), -0.5f));
        const int iz = (int)ceilf(__fadd_rn(__fmul_rn(__fadd_rn(rz, 0.5f), (float)GG), -0.5f));

        int idx = ix * (GG*GG) + iy * GG + iz;
        idx = min(max(idx, 0), G3 - 1);

        rxs[k] = rx; rys[k] = ry; rzs[k] = rz;
        idxs[k] = idx;
    }

    // ---- batched voxel gathers: 12 independent LDGs, MLP=12 ----
    #pragma unroll
    for (int k = 0; k < PP; k++) {
        vs[k] = __ldg(vox_b + idxs[k]);
    }

    // ---- Phase B: masked cp gathers + accumulate ----
    float acc = 0.0f;
    #pragma unroll
    for (int k = 0; k < PP; k++) {
        if (vs[k] == 0.0f) {
            const int idx = idxs[k];
            const float cx = __ldg(cp_b + idx*3 + 0);
            const float cy = __ldg(cp_b + idx*3 + 1);
            const float cz = __ldg(cp_b + idx*3 + 2);
            const float dx = rxs[k] - cx;
            const float dy = rys[k] - cy;
            const float dz = rzs[k] - cz;
            acc += dx*dx + dy*dy + dz*dz;
        }
    }

    // ---- deterministic block reduction ----
    __shared__ float sdata[THREADS];
    sdata[threadIdx.x] = acc;
    __syncthreads();
    #pragma unroll
    for (int stride = THREADS/2; stride >= 32; stride >>= 1) {
        if (threadIdx.x < stride) sdata[threadIdx.x] += sdata[threadIdx.x + stride];
        __syncthreads();
    }
    if (threadIdx.x < 32) {
        float w = sdata[threadIdx.x];
        #pragma unroll
        for (int off = 16; off > 0; off >>= 1)
            w += __shfl_down_sync(0xFFFFFFFF, w, off);
        if (threadIdx.x == 0) g_partials[blockIdx.x] = w;
    }
}

// ---------------------------------------------------------------------------
// Kernel 3: final reduction of NBLOCKS partials, divide by B*P.
// Fixed-order, deterministic.
// ---------------------------------------------------------------------------
__global__ void final_reduce_kernel(float* __restrict__ out) {
    __shared__ float sdata[512];
    const int tid = threadIdx.x;
    float s = 0.0f;
    #pragma unroll 4
    for (int i = tid; i < NBLOCKS; i += 512) s += g_partials[i];
    sdata[tid] = s;
    __syncthreads();
    for (int stride = 256; stride >= 32; stride >>= 1) {
        if (tid < stride) sdata[tid] += sdata[tid + stride];
        __syncthreads();
    }
    if (tid < 32) {
        float w = sdata[tid];
        #pragma unroll
        for (int off = 16; off > 0; off >>= 1)
            w += __shfl_down_sync(0xFFFFFFFF, w, off);
        if (tid == 0) out[0] = w / (float)(BB * PP);
    }
}

// ---------------------------------------------------------------------------
// Inputs (metadata order = setup_inputs dict order):
//   d_in[0] voxel          (B, G, G, G)   float32
//   d_in[1] points         (B, N, 3)      float32
//   d_in[2] closest_points (B, G^3, 3)    float32
//   d_in[3] planes         (B, P, 4)      float32
// Output: scalar float32
// ---------------------------------------------------------------------------
extern "C" void kernel_launch(void* const* d_in, const int* in_sizes, int n_in,
                              void* d_out, int out_size)
{
    const float* voxel  = (const float*)d_in[0];
    const float* points = (const float*)d_in[1];
    const float* cp     = (const float*)d_in[2];
    const float* planes = (const float*)d_in[3];
    float* out = (float*)d_out;

    normalize_planes_kernel<<<1, 128>>>(planes);
    sym_plane_loss_kernel<<<NBLOCKS, THREADS>>>(voxel, points, cp);
    final_reduce_kernel<<<1, 512>>>(out);
}